// round 17
// baseline (speedup 1.0000x reference)
#include <cuda_runtime.h>
#include <cstdint>

// FM second-order term via split-TF32 mma.sync (m16n8k8), single kernel.
//   sum_emb = features @ W  (M=16384, K=200, N=64)
//   per operand: hi = mask13(x), lo = x-hi (regs; HW truncates to tf32)
//   x@W ~ Ah@Bh + Ah@Bl + Al@Bh, fp32 accum.
//   out[b] = sum_e sum_emb[b,e]^2 - sum_f features[b,f]^2 * w2sum[f]
// R17 = R16 engine at 2 CTAs/SM: MTILE=64, 512 thr, smem 112KB/CTA ->
// 32 warps/SM (occ 50%). 16 warps = mg4 x ng4, warp tile m16 x n16,
// full K = 25 k8-steps, raw-B in-loop split, k-banded A staging.

typedef unsigned long long ull;

constexpr int F_DIM = 200;
constexpr int E_DIM = 64;
constexpr int MTILE = 64;
constexpr int THREADS = 512;

constexpr int SA_F = 204;            // A row stride (floats; 816B) 204%32=12
constexpr int SM_A    = 0;           // 64*816  = 52224
constexpr int SM_B    = 52224;       // Braw: 200*288 = 57600 (stride 72 fl)
constexpr int SM_W2S  = 109824;      // 200*4
constexpr int SM_SQS  = 110624;      // 64*4
constexpr int SM_PART = 110880;      // 4*64*4
constexpr int SMEM_TOTAL = 111904;   // <= 116224 -> 2 CTAs/SM

__device__ __forceinline__ uint32_t smem_u32(const void* p) {
    return (uint32_t)__cvta_generic_to_shared(p);
}
__device__ __forceinline__ void cp_async16(uint32_t s, const void* g) {
    asm volatile("cp.async.cg.shared.global [%0], [%1], 16;" :: "r"(s), "l"(g));
}
__device__ __forceinline__ float lds32f(uint32_t a) {
    float v; asm volatile("ld.shared.f32 %0, [%1];" : "=f"(v) : "r"(a)); return v;
}
__device__ __forceinline__ void split13(float x, uint32_t& hi, uint32_t& lo) {
    hi = __float_as_uint(x) & 0xFFFFE000u;
    lo = __float_as_uint(x - __uint_as_float(hi));
}
__device__ __forceinline__ void mma_tf32(float* c, uint32_t a0, uint32_t a1,
                                         uint32_t a2, uint32_t a3,
                                         uint32_t b0, uint32_t b1) {
    asm volatile(
        "mma.sync.aligned.m16n8k8.row.col.f32.tf32.tf32.f32 "
        "{%0,%1,%2,%3}, {%4,%5,%6,%7}, {%8,%9}, {%0,%1,%2,%3};"
        : "+f"(c[0]), "+f"(c[1]), "+f"(c[2]), "+f"(c[3])
        : "r"(a0), "r"(a1), "r"(a2), "r"(a3), "r"(b0), "r"(b1));
}

// stage one A column band [C0, C0+CNT) 16B-chunks for all 64 rows
template <int C0, int CNT>
__device__ __forceinline__ void stage_A_band(uint32_t sb, const float* fblk,
                                             int tid) {
    constexpr int TOT = 64 * CNT;
    #pragma unroll
    for (int i = 0; i < (TOT + THREADS - 1) / THREADS; ++i) {
        const int p = tid + i * THREADS;
        if (TOT % THREADS == 0 || p < TOT) {
            const int row = p / CNT, ch = C0 + (p - row * CNT);
            cp_async16(sb + SM_A + row * 816 + ch * 16,
                       fblk + row * F_DIM + ch * 4);
        }
    }
    asm volatile("cp.async.commit_group;");
}

// one mainloop segment: k8-steps [S0, S1), double-buffered fragments
template <int S0, int S1>
__device__ __forceinline__ void run_seg(uint32_t aB, uint32_t bB,
                                        float c[2][4]) {
    float a_c[4], b_c[4], a_n[4], b_n[4];
    #pragma unroll
    for (int u = 0; u < 2; ++u)
        #pragma unroll
        for (int v = 0; v < 2; ++v)
            a_c[u * 2 + v] =
                lds32f(aB + (uint32_t)(S0 * 32 + v * 16 + u * 8 * SA_F * 4));
    #pragma unroll
    for (int j = 0; j < 2; ++j)
        #pragma unroll
        for (int h = 0; h < 2; ++h)
            b_c[j * 2 + h] =
                lds32f(bB + (uint32_t)((S0 * 8 + h * 4) * 288 + j * 32));

    #pragma unroll
    for (int s = S0; s < S1; ++s) {
        const int sn = (s + 1 < S1) ? s + 1 : S0;   // dummy-wrap in-segment
        #pragma unroll
        for (int u = 0; u < 2; ++u)
            #pragma unroll
            for (int v = 0; v < 2; ++v)
                a_n[u * 2 + v] =
                    lds32f(aB + (uint32_t)(sn * 32 + v * 16 + u * 8 * SA_F * 4));
        #pragma unroll
        for (int j = 0; j < 2; ++j)
            #pragma unroll
            for (int h = 0; h < 2; ++h)
                b_n[j * 2 + h] =
                    lds32f(bB + (uint32_t)((sn * 8 + h * 4) * 288 + j * 32));

        uint32_t ah[4], al[4], bh[4], bl[4];
        #pragma unroll
        for (int q = 0; q < 4; ++q) split13(a_c[q], ah[q], al[q]);
        #pragma unroll
        for (int q = 0; q < 4; ++q) split13(b_c[q], bh[q], bl[q]);

        // 6 MMAs: hh (2 indep accums), hl, lh
        // A operand order: (gr,gk),(gr+8,gk),(gr,gk+4),(gr+8,gk+4)
        mma_tf32(c[0], ah[0], ah[2], ah[1], ah[3], bh[0], bh[1]);
        mma_tf32(c[1], ah[0], ah[2], ah[1], ah[3], bh[2], bh[3]);
        mma_tf32(c[0], ah[0], ah[2], ah[1], ah[3], bl[0], bl[1]);
        mma_tf32(c[1], ah[0], ah[2], ah[1], ah[3], bl[2], bl[3]);
        mma_tf32(c[0], al[0], al[2], al[1], al[3], bh[0], bh[1]);
        mma_tf32(c[1], al[0], al[2], al[1], al[3], bh[2], bh[3]);

        #pragma unroll
        for (int q = 0; q < 4; ++q) { a_c[q] = a_n[q]; b_c[q] = b_n[q]; }
    }
}

__global__ void __launch_bounds__(THREADS, 2)
fm_kernel(const float* __restrict__ features,
          const float* __restrict__ W,
          float* __restrict__ out)
{
    extern __shared__ __align__(16) char smem[];
    const uint32_t sb = smem_u32(smem);
    const int tid = threadIdx.x;
    const int w = tid >> 5, lane = tid & 31;
    const int mg = w >> 2, ng = w & 3;          // warp: rows 16mg, cols 16ng
    const int gr = lane >> 2, gk = lane & 3;

    float* w2s  = (float*)(smem + SM_W2S);
    float* sqs  = (float*)(smem + SM_SQS);
    float* part = (float*)(smem + SM_PART);

    const size_t rowbase = (size_t)blockIdx.x * MTILE;
    const float* fblk = features + rowbase * F_DIM;

    // ---- staging: B (g0, L2-hot broadcast), then A bands (g1,g2,g3)
    #pragma unroll
    for (int i = 0; i < 7; ++i) {
        const int p = tid + i * THREADS;
        if (p < 3200) {
            const int row = p >> 4, ch = p & 15;
            cp_async16(sb + SM_B + row * 288 + ch * 16,
                       W + row * E_DIM + ch * 4);
        }
    }
    asm volatile("cp.async.commit_group;");
    stage_A_band<0, 16>(sb, fblk, tid);    // cols   0..63  -> steps 0..7
    stage_A_band<16, 18>(sb, fblk, tid);   // cols  64..135 -> steps 8..16
    stage_A_band<34, 16>(sb, fblk, tid);   // cols 136..199 -> steps 17..24

    // ---- mainloop bases
    const uint32_t aB = sb + SM_A + (uint32_t)(((16 * mg + gr) * SA_F + gk) * 4);
    const uint32_t bB = sb + SM_B + (uint32_t)((gk * 72 + 16 * ng + gr) * 4);

    float c[2][4];
    #pragma unroll
    for (int j = 0; j < 2; ++j)
        #pragma unroll
        for (int q = 0; q < 4; ++q) c[j][q] = 0.f;

    asm volatile("cp.async.wait_group 2;" ::: "memory");
    __syncthreads();
    run_seg<0, 8>(aB, bB, c);

    asm volatile("cp.async.wait_group 1;" ::: "memory");
    __syncthreads();
    run_seg<8, 17>(aB, bB, c);

    asm volatile("cp.async.wait_group 0;" ::: "memory");
    __syncthreads();
    run_seg<17, 25>(aB, bB, c);

    // ---- epilogue: rows 16mg+gr and +8, sum of squares over 16 cols
    {
        float s_lo = c[0][0] * c[0][0] + c[0][1] * c[0][1]
                   + c[1][0] * c[1][0] + c[1][1] * c[1][1];
        float s_hi = c[0][2] * c[0][2] + c[0][3] * c[0][3]
                   + c[1][2] * c[1][2] + c[1][3] * c[1][3];
        s_lo += __shfl_xor_sync(0xffffffffu, s_lo, 1);
        s_lo += __shfl_xor_sync(0xffffffffu, s_lo, 2);
        s_hi += __shfl_xor_sync(0xffffffffu, s_hi, 1);
        s_hi += __shfl_xor_sync(0xffffffffu, s_hi, 2);
        if (gk == 0) {
            part[ng * 64 + 16 * mg + gr] = s_lo;
            part[ng * 64 + 16 * mg + 8 + gr] = s_hi;
        }
    }

    // ---- w2sum from Braw smem (LDS only)
    if (tid < F_DIM) {
        float s = 0.f;
        #pragma unroll
        for (int i = 0; i < 16; ++i) {
            const float4 v = *(const float4*)(smem + SM_B + tid * 288 + i * 16);
            s = fmaf(v.x, v.x, s); s = fmaf(v.y, v.y, s);
            s = fmaf(v.z, v.z, s); s = fmaf(v.w, v.w, s);
        }
        w2s[tid] = s;
    }
    __syncthreads();

    // ---- sq term from smem A (raw fp32, exact): 8 threads per row
    {
        const int row = tid >> 3, q = tid & 7;
        const uint32_t aRow = sb + SM_A + (uint32_t)(row * 816);
        float s0 = 0.f;
        #pragma unroll
        for (int j = 0; j < 25; ++j) {
            const int f = q + 8 * j;
            const float x = lds32f(aRow + f * 4);
            s0 = fmaf(x * x, w2s[f], s0);
        }
        s0 += __shfl_xor_sync(0xffffffffu, s0, 1);
        s0 += __shfl_xor_sync(0xffffffffu, s0, 2);
        s0 += __shfl_xor_sync(0xffffffffu, s0, 4);
        if (q == 0) sqs[row] = s0;
    }
    __syncthreads();

    if (tid < MTILE)
        out[rowbase + tid] = part[tid] + part[64 + tid] + part[128 + tid] +
                             part[192 + tid] - sqs[tid];
}

extern "C" void kernel_launch(void* const* d_in, const int* in_sizes, int n_in,
                              void* d_out, int out_size)
{
    const float* features = (const float*)d_in[0];
    const float* W        = (const float*)d_in[1];
    if (n_in >= 2 && in_sizes[0] < in_sizes[1]) {
        features = (const float*)d_in[1];
        W        = (const float*)d_in[0];
    }
    float* out = (float*)d_out;

    cudaFuncSetAttribute(fm_kernel,
                         cudaFuncAttributeMaxDynamicSharedMemorySize, SMEM_TOTAL);

    const int B = out_size;              // 16384
    const int blocks = B / MTILE;        // 256 -> 2 CTAs/SM, single wave
    fm_kernel<<<blocks, THREADS, SMEM_TOTAL>>>(features, W, out);
}